// round 15
// baseline (speedup 1.0000x reference)
#include <cuda_runtime.h>
#include <cuda_fp16.h>
#include <cstdint>

#define BB   16
#define CIN  512
#define HH   40
#define WW   40
#define HW   1600
#define NTOK 80
#define CG   512
#define EE   256
#define COUT 512
#define NH   8
#define HC   32
#define BN_EPS 1e-3f
// 41-stride shared-pad pixel space: pi = r*41 + c, slot c=40 of each row = shared pad
#define PBUF 1792
#define XOFF 64

// ------------------------------ scratch (device globals) -------------------
__device__ float g_buf[BB * NTOK * EE];
__device__ float attn_buf[BB * NH * HW];
__device__ __align__(256) __half xp_hi[(size_t)BB * PBUF * CIN];
__device__ __align__(256) __half wk_h[(size_t)9 * COUT * CIN];
__device__ __align__(256) __half we_h[EE * CIN];

// ------------------------------ helpers ------------------------------------
__device__ __forceinline__ uint32_t smem_u32(const void* p) {
    uint32_t a;
    asm("{ .reg .u64 t; cvta.to.shared.u64 t, %1; cvt.u32.u64 %0, t; }" : "=r"(a) : "l"(p));
    return a;
}
#define SW128(off) ((off) ^ (((off) >> 3) & 0x70))

__device__ __forceinline__ void cp16(uint32_t dst, const void* src) {
    asm volatile("cp.async.cg.shared.global [%0], [%1], 16;" :: "r"(dst), "l"(src));
}

#define LDSM_X4(r, a) \
    asm volatile("ldmatrix.sync.aligned.m8n8.x4.shared.b16 {%0,%1,%2,%3}, [%4];" \
        : "=r"((r)[0]), "=r"((r)[1]), "=r"((r)[2]), "=r"((r)[3]) : "r"(a))

#define MMA16816(d, a, b0, b1) \
    asm volatile("mma.sync.aligned.m16n8k16.row.col.f32.f16.f16.f32 " \
        "{%0,%1,%2,%3}, {%4,%5,%6,%7}, {%8,%9}, {%0,%1,%2,%3};" \
        : "+f"((d)[0]), "+f"((d)[1]), "+f"((d)[2]), "+f"((d)[3]) \
        : "r"((a)[0]), "r"((a)[1]), "r"((a)[2]), "r"((a)[3]), "r"(b0), "r"(b1))

// ====== merged prep: xprep (5120 blocks) + W/We/guide (1088 blocks) =========
__global__ void prep_all(const float* __restrict__ x,
                         const float* __restrict__ Wp, const float* __restrict__ We,
                         const float* __restrict__ guide, const float* __restrict__ Wg,
                         const float* __restrict__ bg) {
    int id = blockIdx.x;
    if (id < 5120) {
        // ---- xprep: x(r,c) -> padded fp16 at pi = r*41 + c ----
        __shared__ float s[64][41];
        int r  = id % 40;
        int cc = ((id / 40) & 7) * 64;
        int b  = id / 320;
        for (int idx = threadIdx.x; idx < 64 * 40; idx += 256) {
            int ci = idx / 40, c = idx % 40;
            s[ci][c] = x[((size_t)(b * CIN + cc + ci)) * HW + r * WW + c];
        }
        __syncthreads();
        for (int idx = threadIdx.x; idx < 41 * 8; idx += 256) {
            int c = idx >> 3, cg = idx & 7;
            __half h8[8];
            #pragma unroll
            for (int j = 0; j < 8; j++)
                h8[j] = __float2half((c < 40) ? s[cg * 8 + j][c] : 0.f);
            size_t off = ((size_t)b * PBUF + XOFF + r * 41 + c) * CIN + cc + cg * 8;
            *reinterpret_cast<uint4*>(&xp_hi[off]) = *reinterpret_cast<const uint4*>(h8);
        }
        if (r == 0) {
            uint4 z = {0, 0, 0, 0};
            for (int idx = threadIdx.x; idx < 152 * 8; idx += 256) {
                int sl = idx >> 3, cg = idx & 7;
                int slot = (sl < XOFF) ? sl : (XOFF + 1640 + sl - XOFF);
                *reinterpret_cast<uint4*>(&xp_hi[((size_t)b * PBUF + slot) * CIN + cc + cg * 8]) = z;
            }
        }
        return;
    }
    int bid = id - 5120;
    if (bid < COUT) {
        int co = bid;
        for (int ci = threadIdx.x; ci < CIN; ci += 256) {
            const float* src = Wp + ((size_t)co * CIN + ci) * 9;
            #pragma unroll
            for (int k = 0; k < 9; k++)
                wk_h[((size_t)k * COUT + co) * CIN + ci] = __float2half(src[k]);
        }
        return;
    }
    if (bid < COUT + EE) {
        int e = bid - COUT;
        for (int ci = threadIdx.x; ci < CIN; ci += 256)
            we_h[(size_t)e * CIN + ci] = __float2half(We[(size_t)e * CIN + ci]);
        return;
    }
    // guide FC: 320 blocks (40 x 8)
    int gb = bid - COUT - EE;
    int row0 = (gb % 40) * 32;
    int col0 = (gb / 40) * 32;
    __shared__ float As[32][33];
    __shared__ float Bs[32][33];
    int tid = threadIdx.x;
    int tx = tid & 31, ty = tid >> 5;
    float acc[4] = {0.f, 0.f, 0.f, 0.f};
    for (int kc = 0; kc < CG; kc += 32) {
        int r = tid >> 3, kq = (tid & 7) * 4;
        float4 a4 = *reinterpret_cast<const float4*>(&guide[(size_t)(row0 + r) * CG + kc + kq]);
        As[r][kq] = a4.x; As[r][kq + 1] = a4.y; As[r][kq + 2] = a4.z; As[r][kq + 3] = a4.w;
        float4 b4 = *reinterpret_cast<const float4*>(&Wg[(size_t)(col0 + r) * CG + kc + kq]);
        Bs[r][kq] = b4.x; Bs[r][kq + 1] = b4.y; Bs[r][kq + 2] = b4.z; Bs[r][kq + 3] = b4.w;
        __syncthreads();
        #pragma unroll
        for (int k = 0; k < 32; k++) {
            float bv = Bs[tx][k];
            #pragma unroll
            for (int rr = 0; rr < 4; rr++)
                acc[rr] += As[ty + 8 * rr][k] * bv;
        }
        __syncthreads();
    }
    float bias = bg[col0 + tx];
    #pragma unroll
    for (int rr = 0; rr < 4; rr++)
        g_buf[(size_t)(row0 + ty + 8 * rr) * EE + col0 + tx] = acc[rr] + bias;
}

// =============== conv: CTA 128(M) x 128(N), 8 warps 64x32, 2 CTAs/SM ========
#define C_BHI  16384
#define CSTG   32768       // A 16K | B 16K
#define CSMEM  98304       // 3 stages
#define CNSTEP 72

struct FragC { float acc[4][4][4]; };

__device__ __forceinline__ void conv_load(uint32_t sb, int s, int cobase,
                                          int q0, int b, int tid) {
    int k = s >> 3, cc = s & 7;
    int kh = k / 3, kw = k - kh * 3;
    uint32_t st = sb + (uint32_t)(s % 3) * CSTG;
    const char* a_src = (const char*)(wk_h + ((size_t)k * COUT + cobase) * CIN + cc * 64);
    size_t xoff = ((size_t)b * PBUF + XOFF + q0 + (kh - 1) * 41 + (kw - 1)) * CIN + cc * 64;
    const char* b_src = (const char*)(xp_hi + xoff);
    #pragma unroll
    for (int i = 0; i < 4; i++) {
        int id = tid + i * 256;
        int row = id >> 3, ch = id & 7;
        cp16(st + SW128(row * 128 + ch * 16), a_src + (size_t)row * 1024 + ch * 16);
    }
    #pragma unroll
    for (int i = 0; i < 4; i++) {
        int id = tid + i * 256;
        int row = id >> 3, ch = id & 7;
        cp16(st + C_BHI + SW128(row * 128 + ch * 16), b_src + (size_t)row * 1024 + ch * 16);
    }
    asm volatile("cp.async.commit_group;" ::: "memory");
}

__device__ __forceinline__ void mma_stepC(uint32_t st, int wm, int wn, int lane,
                                          FragC& f) {
    int lr    = lane & 15;
    int ahalf = ((lane >> 4) & 1) * 16;
    int brow  = ((lane >> 4) & 1) * 8 + (lane & 7);
    int bhalf = ((lane >> 3) & 1) * 16;
    uint32_t bh[4][2][4];
    #pragma unroll
    for (int kk = 0; kk < 4; kk++)
        #pragma unroll
        for (int bt = 0; bt < 2; bt++) {
            uint32_t off = SW128((uint32_t)(wn * 32 + bt * 16 + brow) * 128 + kk * 32 + bhalf);
            LDSM_X4(bh[kk][bt], st + C_BHI + off);
        }
    #pragma unroll
    for (int kk = 0; kk < 4; kk++) {
        #pragma unroll
        for (int mt = 0; mt < 4; mt++) {
            uint32_t a[4];
            uint32_t off = SW128((uint32_t)(wm * 64 + mt * 16 + lr) * 128 + kk * 32 + ahalf);
            LDSM_X4(a, st + off);
            #pragma unroll
            for (int nt = 0; nt < 4; nt++) {
                int bt = nt >> 1, pp = (nt & 1) * 2;
                MMA16816(f.acc[mt][nt], a, bh[kk][bt][pp], bh[kk][bt][pp + 1]);
            }
        }
    }
}

__global__ void __launch_bounds__(256, 2)
conv_mma(const float* __restrict__ gamma_p,
         const float* __restrict__ beta_p,
         float* __restrict__ out) {
    extern __shared__ __align__(1024) char smem[];
    uint32_t sb = smem_u32(smem);
    int tid = threadIdx.x, wid = tid >> 5, lane = tid & 31;
    int q0     = blockIdx.x * 128;
    int cobase = blockIdx.y * 128;
    int b      = blockIdx.z;
    int wm = wid >> 2, wn = wid & 3;

    FragC f;
    #pragma unroll
    for (int mt = 0; mt < 4; mt++)
        #pragma unroll
        for (int nt = 0; nt < 4; nt++)
            #pragma unroll
            for (int r = 0; r < 4; r++) f.acc[mt][nt][r] = 0.f;

    conv_load(sb, 0, cobase, q0, b, tid);
    conv_load(sb, 1, cobase, q0, b, tid);
    for (int s = 0; s < CNSTEP; s++) {
        if (s + 1 < CNSTEP) asm volatile("cp.async.wait_group 1;" ::: "memory");
        else                asm volatile("cp.async.wait_group 0;" ::: "memory");
        __syncthreads();
        if (s + 2 < CNSTEP) conv_load(sb, s + 2, cobase, q0, b, tid);
        mma_stepC(sb + (uint32_t)(s % 3) * CSTG, wm, wn, lane, f);
    }

    int head = (cobase >> 6) + wm;
    int qb = q0 + wn * 32;
    float inv = rsqrtf(1.0f + BN_EPS);
    float av[4][2];
    int hwv[4][2];
    #pragma unroll
    for (int nt = 0; nt < 4; nt++) {
        #pragma unroll
        for (int e = 0; e < 2; e++) {
            int qq = qb + nt * 8 + (lane & 3) * 2 + e;
            int pr = qq / 41, pc = qq - pr * 41;
            bool ok = (pc < 40 && pr < 40);
            int hw = pr * 40 + pc;
            hwv[nt][e] = ok ? hw : -1;
            av[nt][e] = ok ? attn_buf[(size_t)(b * NH + head) * HW + hw] : 0.f;
        }
    }
    #pragma unroll
    for (int mt = 0; mt < 4; mt++) {
        int r0 = cobase + wm * 64 + mt * 16 + (lane >> 2);
        float sc0 = gamma_p[r0] * inv,     bt0 = beta_p[r0];
        float sc8 = gamma_p[r0 + 8] * inv, bt8 = beta_p[r0 + 8];
        #pragma unroll
        for (int nt = 0; nt < 4; nt++) {
            #pragma unroll
            for (int e = 0; e < 2; e++) {
                int hw = hwv[nt][e];
                if (hw >= 0) {
                    out[((size_t)(b * COUT + r0)) * HW + hw]     = (f.acc[mt][nt][e]     * sc0 + bt0) * av[nt][e];
                    out[((size_t)(b * COUT + r0 + 8)) * HW + hw] = (f.acc[mt][nt][e + 2] * sc8 + bt8) * av[nt][e];
                }
            }
        }
    }
}

// ====== embed 1x1 (M=256=all E, N=64 q) + MMA attn: 256 thr, 2 CTAs/SM =====
#define E_BHI  32768
#define ESTG   40960       // A 32K | B 8K
#define ENSTEP 8
#define TSH 264                          // fp16 tile row stride (halves)
#define GSH_OFF (64 * TSH)               // g region offset (halves)
#define ESMEM 81920

struct FragE { float acc[4][4][4]; };

__device__ __forceinline__ void embed_load(uint32_t sb, int s, int q0, int b, int tid) {
    uint32_t st = sb + (uint32_t)(s & 1) * ESTG;
    const char* a_src = (const char*)(we_h + s * 64);
    size_t xoff = ((size_t)b * PBUF + XOFF + q0) * CIN + s * 64;
    const char* b_src = (const char*)(xp_hi + xoff);
    #pragma unroll
    for (int i = 0; i < 8; i++) {
        int id = tid + i * 256;
        int row = id >> 3, ch = id & 7;
        cp16(st + SW128(row * 128 + ch * 16), a_src + (size_t)row * 1024 + ch * 16);
    }
    #pragma unroll
    for (int i = 0; i < 2; i++) {
        int id = tid + i * 256;
        int row = id >> 3, ch = id & 7;
        cp16(st + E_BHI + SW128(row * 128 + ch * 16), b_src + (size_t)row * 1024 + ch * 16);
    }
    asm volatile("cp.async.commit_group;" ::: "memory");
}

__device__ __forceinline__ void mma_stepE(uint32_t st, int wm, int wn, int lane,
                                          FragE& f) {
    int lr    = lane & 15;
    int ahalf = ((lane >> 4) & 1) * 16;
    int brow  = ((lane >> 4) & 1) * 8 + (lane & 7);
    int bhalf = ((lane >> 3) & 1) * 16;
    #pragma unroll
    for (int kk = 0; kk < 4; kk++) {
        uint32_t bh[2][4];
        #pragma unroll
        for (int bt = 0; bt < 2; bt++) {
            uint32_t off = SW128((uint32_t)(wn * 32 + bt * 16 + brow) * 128 + kk * 32 + bhalf);
            LDSM_X4(bh[bt], st + E_BHI + off);
        }
        #pragma unroll
        for (int mt = 0; mt < 4; mt++) {
            uint32_t a[4];
            uint32_t off = SW128((uint32_t)(wm * 64 + mt * 16 + lr) * 128 + kk * 32 + ahalf);
            LDSM_X4(a, st + off);
            #pragma unroll
            for (int nt = 0; nt < 4; nt++) {
                int bt = nt >> 1, pp = (nt & 1) * 2;
                MMA16816(f.acc[mt][nt], a, bh[bt][pp], bh[bt][pp + 1]);
            }
        }
    }
}

__global__ void __launch_bounds__(256, 2)
embed_attn(const float* __restrict__ gamma_e,
           const float* __restrict__ beta_e,
           const float* __restrict__ head_bias) {
    extern __shared__ __align__(1024) char smem[];
    uint32_t sb = smem_u32(smem);
    int tid = threadIdx.x, wid = tid >> 5, lane = tid & 31;
    int q0 = blockIdx.x * 64;
    int b  = blockIdx.z;
    int wm = wid >> 1, wn = wid & 1;      // warp tile 64(E) x 32(q)

    FragE f;
    #pragma unroll
    for (int mt = 0; mt < 4; mt++)
        #pragma unroll
        for (int nt = 0; nt < 4; nt++)
            #pragma unroll
            for (int r = 0; r < 4; r++) f.acc[mt][nt][r] = 0.f;

    embed_load(sb, 0, q0, b, tid);
    for (int s = 0; s < ENSTEP; s++) {
        asm volatile("cp.async.wait_group 0;" ::: "memory");
        __syncthreads();
        if (s + 1 < ENSTEP) embed_load(sb, s + 1, q0, b, tid);
        mma_stepE(sb + (uint32_t)(s & 1) * ESTG, wm, wn, lane, f);
    }
    __syncthreads();   // stage buffers reused below

    // BN + write fp16 tile[q][e]
    __half* tile = reinterpret_cast<__half*>(smem);
    __half* gsm  = tile + GSH_OFF;
    float inv = rsqrtf(1.0f + BN_EPS);
    #pragma unroll
    for (int mt = 0; mt < 4; mt++) {
        int er = wm * 64 + mt * 16 + (lane >> 2);
        float sc0 = gamma_e[er] * inv,     bt0 = beta_e[er];
        float sc8 = gamma_e[er + 8] * inv, bt8 = beta_e[er + 8];
        #pragma unroll
        for (int nt = 0; nt < 4; nt++) {
            int ql = wn * 32 + nt * 8 + (lane & 3) * 2;
            tile[ql * TSH + er]           = __float2half(f.acc[mt][nt][0] * sc0 + bt0);
            tile[(ql + 1) * TSH + er]     = __float2half(f.acc[mt][nt][1] * sc0 + bt0);
            tile[ql * TSH + er + 8]       = __float2half(f.acc[mt][nt][2] * sc8 + bt8);
            tile[(ql + 1) * TSH + er + 8] = __float2half(f.acc[mt][nt][3] * sc8 + bt8);
        }
    }
    {
        const float* gsrc = g_buf + (size_t)b * NTOK * EE;
        for (int i = tid; i < NTOK * EE / 4; i += 256) {
            int n = i >> 6, eq = (i & 63) * 4;
            float4 v = reinterpret_cast<const float4*>(gsrc)[i];
            __half h4[4] = {__float2half(v.x), __float2half(v.y),
                            __float2half(v.z), __float2half(v.w)};
            *reinterpret_cast<uint2*>(&gsm[n * TSH + eq]) = *reinterpret_cast<const uint2*>(h4);
        }
    }
    __syncthreads();

    // ---- MMA attention scores: warp = head m, covers all 64 q ----
    int m  = wid;
    uint32_t tb = sb;
    uint32_t gb = sb + GSH_OFF * 2;
    int lr = lane & 15;
    int ah16 = ((lane >> 4) & 1) * 16;
    int brow = ((lane >> 4) & 1) * 8 + (lane & 7);
    int bh16 = ((lane >> 3) & 1) * 16;

    uint32_t a[4][2][4];
    #pragma unroll
    for (int mt = 0; mt < 4; mt++)
        #pragma unroll
        for (int kk = 0; kk < 2; kk++) {
            uint32_t addr = tb + (uint32_t)(mt * 16 + lr) * (TSH * 2)
                          + (m * 32 + kk * 16) * 2 + ah16;
            LDSM_X4(a[mt][kk], addr);
        }

    float rmax[4][2];
    #pragma unroll
    for (int mt = 0; mt < 4; mt++) { rmax[mt][0] = -3.4e38f; rmax[mt][1] = -3.4e38f; }

    #pragma unroll
    for (int nt16 = 0; nt16 < 5; nt16++) {
        uint32_t b0[4], b1[4];
        uint32_t baddr = gb + (uint32_t)(nt16 * 16 + brow) * (TSH * 2) + m * 32 * 2 + bh16;
        LDSM_X4(b0, baddr);
        LDSM_X4(b1, baddr + 32);
        #pragma unroll
        for (int sub = 0; sub < 2; sub++) {
            #pragma unroll
            for (int mt = 0; mt < 4; mt++) {
                float acc[4] = {0.f, 0.f, 0.f, 0.f};
                MMA16816(acc, a[mt][0], b0[sub * 2], b0[sub * 2 + 1]);
                MMA16816(acc, a[mt][1], b1[sub * 2], b1[sub * 2 + 1]);
                rmax[mt][0] = fmaxf(rmax[mt][0], fmaxf(acc[0], acc[1]));
                rmax[mt][1] = fmaxf(rmax[mt][1], fmaxf(acc[2], acc[3]));
            }
        }
    }

    float hb = head_bias[m];
    #pragma unroll
    for (int mt = 0; mt < 4; mt++) {
        #pragma unroll
        for (int r01 = 0; r01 < 2; r01++) {
            float v = rmax[mt][r01];
            v = fmaxf(v, __shfl_xor_sync(0xFFFFFFFFu, v, 1));
            v = fmaxf(v, __shfl_xor_sync(0xFFFFFFFFu, v, 2));
            if ((lane & 3) == 0) {
                int qq = q0 + mt * 16 + (lane >> 2) + r01 * 8;
                int pr = qq / 41, pc = qq - pr * 41;
                if (pc < 40 && pr < 40) {
                    float aa = v * 0.17677669529663687f + hb;
                    float s = 1.0f / (1.0f + __expf(-aa));
                    attn_buf[(size_t)(b * NH + m) * HW + pr * 40 + pc] = s;
                }
            }
        }
    }
}

extern "C" void kernel_launch(void* const* d_in, const int* in_sizes, int n_in,
                              void* d_out, int out_size) {
    const float* x         = (const float*)d_in[0];
    const float* guide     = (const float*)d_in[1];
    const float* We        = (const float*)d_in[2];
    const float* gamma_e   = (const float*)d_in[3];
    const float* beta_e    = (const float*)d_in[4];
    const float* Wg        = (const float*)d_in[5];
    const float* bg        = (const float*)d_in[6];
    const float* head_bias = (const float*)d_in[7];
    const float* Wp        = (const float*)d_in[8];
    const float* gamma_p   = (const float*)d_in[9];
    const float* beta_p    = (const float*)d_in[10];
    float* out = (float*)d_out;

    prep_all<<<5120 + COUT + EE + 320, 256>>>(x, Wp, We, guide, Wg, bg);
    cudaFuncSetAttribute(embed_attn, cudaFuncAttributeMaxDynamicSharedMemorySize, ESMEM);
    embed_attn<<<dim3(26, 1, 16), 256, ESMEM>>>(gamma_e, beta_e, head_bias);
    cudaFuncSetAttribute(conv_mma, cudaFuncAttributeMaxDynamicSharedMemorySize, CSMEM);
    conv_mma<<<dim3(13, 4, 16), 256, CSMEM>>>(gamma_p, beta_p, out);
}

// round 16
// speedup vs baseline: 1.0654x; 1.0654x over previous
#include <cuda_runtime.h>
#include <cuda_fp16.h>
#include <cstdint>

#define BB   16
#define CIN  512
#define HH   40
#define WW   40
#define HW   1600
#define NTOK 80
#define CG   512
#define EE   256
#define COUT 512
#define NH   8
#define HC   32
#define BN_EPS 1e-3f
// 41-stride shared-pad pixel space: pi = r*41 + c, slot c=40 of each row = shared pad
#define PBUF 1792
#define XOFF 64

// ------------------------------ scratch (device globals) -------------------
__device__ float g_buf[BB * NTOK * EE];
__device__ float attn_buf[BB * NH * HW];
__device__ __align__(256) __half xp_hi[(size_t)BB * PBUF * CIN];
__device__ __align__(256) __half wk_h[(size_t)9 * COUT * CIN];
__device__ __align__(256) __half we_h[EE * CIN];

// ------------------------------ helpers ------------------------------------
__device__ __forceinline__ uint32_t smem_u32(const void* p) {
    uint32_t a;
    asm("{ .reg .u64 t; cvta.to.shared.u64 t, %1; cvt.u32.u64 %0, t; }" : "=r"(a) : "l"(p));
    return a;
}
#define SW128(off) ((off) ^ (((off) >> 3) & 0x70))

__device__ __forceinline__ void cp16(uint32_t dst, const void* src) {
    asm volatile("cp.async.cg.shared.global [%0], [%1], 16;" :: "r"(dst), "l"(src));
}

#define LDSM_X4(r, a) \
    asm volatile("ldmatrix.sync.aligned.m8n8.x4.shared.b16 {%0,%1,%2,%3}, [%4];" \
        : "=r"((r)[0]), "=r"((r)[1]), "=r"((r)[2]), "=r"((r)[3]) : "r"(a))

#define MMA16816(d, a, b0, b1) \
    asm volatile("mma.sync.aligned.m16n8k16.row.col.f32.f16.f16.f32 " \
        "{%0,%1,%2,%3}, {%4,%5,%6,%7}, {%8,%9}, {%0,%1,%2,%3};" \
        : "+f"((d)[0]), "+f"((d)[1]), "+f"((d)[2]), "+f"((d)[3]) \
        : "r"((a)[0]), "r"((a)[1]), "r"((a)[2]), "r"((a)[3]), "r"(b0), "r"(b1))

// -------- merged prep: Wp -> wk_h, We -> we_h, guide FC -> g_buf ------------
__global__ void prep_wg(const float* __restrict__ Wp, const float* __restrict__ We,
                        const float* __restrict__ guide, const float* __restrict__ Wg,
                        const float* __restrict__ bg) {
    int bid = blockIdx.x;
    if (bid < COUT) {
        int co = bid;
        for (int ci = threadIdx.x; ci < CIN; ci += 256) {
            const float* src = Wp + ((size_t)co * CIN + ci) * 9;
            #pragma unroll
            for (int k = 0; k < 9; k++)
                wk_h[((size_t)k * COUT + co) * CIN + ci] = __float2half(src[k]);
        }
        return;
    }
    if (bid < COUT + EE) {
        int e = bid - COUT;
        for (int ci = threadIdx.x; ci < CIN; ci += 256)
            we_h[(size_t)e * CIN + ci] = __float2half(We[(size_t)e * CIN + ci]);
        return;
    }
    int gb = bid - COUT - EE;
    int row0 = (gb % 40) * 32;
    int col0 = (gb / 40) * 32;
    __shared__ float As[32][33];
    __shared__ float Bs[32][33];
    int tid = threadIdx.x;
    int tx = tid & 31, ty = tid >> 5;
    float acc[4] = {0.f, 0.f, 0.f, 0.f};
    for (int kc = 0; kc < CG; kc += 32) {
        int r = tid >> 3, kq = (tid & 7) * 4;
        float4 a4 = *reinterpret_cast<const float4*>(&guide[(size_t)(row0 + r) * CG + kc + kq]);
        As[r][kq] = a4.x; As[r][kq + 1] = a4.y; As[r][kq + 2] = a4.z; As[r][kq + 3] = a4.w;
        float4 b4 = *reinterpret_cast<const float4*>(&Wg[(size_t)(col0 + r) * CG + kc + kq]);
        Bs[r][kq] = b4.x; Bs[r][kq + 1] = b4.y; Bs[r][kq + 2] = b4.z; Bs[r][kq + 3] = b4.w;
        __syncthreads();
        #pragma unroll
        for (int k = 0; k < 32; k++) {
            float bv = Bs[tx][k];
            #pragma unroll
            for (int rr = 0; rr < 4; rr++)
                acc[rr] += As[ty + 8 * rr][k] * bv;
        }
        __syncthreads();
    }
    float bias = bg[col0 + tx];
    #pragma unroll
    for (int rr = 0; rr < 4; rr++)
        g_buf[(size_t)(row0 + ty + 8 * rr) * EE + col0 + tx] = acc[rr] + bias;
}

// x(r,c) -> padded fp16 at pi = r*41 + c; vectorized 16B stores; pads included
__global__ void xprep(const float* __restrict__ x) {
    __shared__ float s[64][41];
    int r  = blockIdx.x;
    int cc = blockIdx.y * 64;
    int b  = blockIdx.z;
    for (int idx = threadIdx.x; idx < 64 * 40; idx += 256) {
        int ci = idx / 40, c = idx % 40;
        s[ci][c] = x[((size_t)(b * CIN + cc + ci)) * HW + r * WW + c];
    }
    __syncthreads();
    for (int idx = threadIdx.x; idx < 41 * 8; idx += 256) {
        int c = idx >> 3, cg = idx & 7;
        __half h8[8];
        #pragma unroll
        for (int j = 0; j < 8; j++)
            h8[j] = __float2half((c < 40) ? s[cg * 8 + j][c] : 0.f);
        size_t off = ((size_t)b * PBUF + XOFF + r * 41 + c) * CIN + cc + cg * 8;
        *reinterpret_cast<uint4*>(&xp_hi[off]) = *reinterpret_cast<const uint4*>(h8);
    }
    if (r == 0) {
        uint4 z = {0, 0, 0, 0};
        for (int idx = threadIdx.x; idx < 152 * 8; idx += 256) {
            int sl = idx >> 3, cg = idx & 7;
            int slot = (sl < XOFF) ? sl : (XOFF + 1640 + sl - XOFF);
            *reinterpret_cast<uint4*>(&xp_hi[((size_t)b * PBUF + slot) * CIN + cc + cg * 8]) = z;
        }
    }
}

// =============== conv: CTA 128(M) x 128(N), 8 warps 64x32, 2 CTAs/SM ========
#define C_BHI  16384
#define CSTG   32768       // A 16K | B 16K
#define CSMEM  98304       // 3 stages
#define CNSTEP 72

struct FragC { float acc[4][4][4]; };

__device__ __forceinline__ void conv_load(uint32_t sb, int s, int cobase,
                                          int q0, int b, int tid) {
    int k = s >> 3, cc = s & 7;
    int kh = k / 3, kw = k - kh * 3;
    uint32_t st = sb + (uint32_t)(s % 3) * CSTG;
    const char* a_src = (const char*)(wk_h + ((size_t)k * COUT + cobase) * CIN + cc * 64);
    size_t xoff = ((size_t)b * PBUF + XOFF + q0 + (kh - 1) * 41 + (kw - 1)) * CIN + cc * 64;
    const char* b_src = (const char*)(xp_hi + xoff);
    #pragma unroll
    for (int i = 0; i < 4; i++) {
        int id = tid + i * 256;
        int row = id >> 3, ch = id & 7;
        cp16(st + SW128(row * 128 + ch * 16), a_src + (size_t)row * 1024 + ch * 16);
    }
    #pragma unroll
    for (int i = 0; i < 4; i++) {
        int id = tid + i * 256;
        int row = id >> 3, ch = id & 7;
        cp16(st + C_BHI + SW128(row * 128 + ch * 16), b_src + (size_t)row * 1024 + ch * 16);
    }
    asm volatile("cp.async.commit_group;" ::: "memory");
}

__device__ __forceinline__ void mma_stepC(uint32_t st, int wm, int wn, int lane,
                                          FragC& f) {
    int lr    = lane & 15;
    int ahalf = ((lane >> 4) & 1) * 16;
    int brow  = ((lane >> 4) & 1) * 8 + (lane & 7);
    int bhalf = ((lane >> 3) & 1) * 16;
    uint32_t bh[4][2][4];
    #pragma unroll
    for (int kk = 0; kk < 4; kk++)
        #pragma unroll
        for (int bt = 0; bt < 2; bt++) {
            uint32_t off = SW128((uint32_t)(wn * 32 + bt * 16 + brow) * 128 + kk * 32 + bhalf);
            LDSM_X4(bh[kk][bt], st + C_BHI + off);
        }
    #pragma unroll
    for (int kk = 0; kk < 4; kk++) {
        #pragma unroll
        for (int mt = 0; mt < 4; mt++) {
            uint32_t a[4];
            uint32_t off = SW128((uint32_t)(wm * 64 + mt * 16 + lr) * 128 + kk * 32 + ahalf);
            LDSM_X4(a, st + off);
            #pragma unroll
            for (int nt = 0; nt < 4; nt++) {
                int bt = nt >> 1, pp = (nt & 1) * 2;
                MMA16816(f.acc[mt][nt], a, bh[kk][bt][pp], bh[kk][bt][pp + 1]);
            }
        }
    }
}

__global__ void __launch_bounds__(256, 2)
conv_mma(const float* __restrict__ gamma_p,
         const float* __restrict__ beta_p,
         float* __restrict__ out) {
    extern __shared__ __align__(1024) char smem[];
    uint32_t sb = smem_u32(smem);
    int tid = threadIdx.x, wid = tid >> 5, lane = tid & 31;
    int q0     = blockIdx.x * 128;
    int cobase = blockIdx.y * 128;
    int b      = blockIdx.z;
    int wm = wid >> 2, wn = wid & 3;

    FragC f;
    #pragma unroll
    for (int mt = 0; mt < 4; mt++)
        #pragma unroll
        for (int nt = 0; nt < 4; nt++)
            #pragma unroll
            for (int r = 0; r < 4; r++) f.acc[mt][nt][r] = 0.f;

    conv_load(sb, 0, cobase, q0, b, tid);
    conv_load(sb, 1, cobase, q0, b, tid);
    for (int s = 0; s < CNSTEP; s++) {
        if (s + 1 < CNSTEP) asm volatile("cp.async.wait_group 1;" ::: "memory");
        else                asm volatile("cp.async.wait_group 0;" ::: "memory");
        __syncthreads();
        if (s + 2 < CNSTEP) conv_load(sb, s + 2, cobase, q0, b, tid);
        mma_stepC(sb + (uint32_t)(s % 3) * CSTG, wm, wn, lane, f);
    }

    int head = (cobase >> 6) + wm;
    int qb = q0 + wn * 32;
    float inv = rsqrtf(1.0f + BN_EPS);
    float av[4][2];
    int hwv[4][2];
    #pragma unroll
    for (int nt = 0; nt < 4; nt++) {
        #pragma unroll
        for (int e = 0; e < 2; e++) {
            int qq = qb + nt * 8 + (lane & 3) * 2 + e;
            int pr = qq / 41, pc = qq - pr * 41;
            bool ok = (pc < 40 && pr < 40);
            int hw = pr * 40 + pc;
            hwv[nt][e] = ok ? hw : -1;
            av[nt][e] = ok ? attn_buf[(size_t)(b * NH + head) * HW + hw] : 0.f;
        }
    }
    #pragma unroll
    for (int mt = 0; mt < 4; mt++) {
        int r0 = cobase + wm * 64 + mt * 16 + (lane >> 2);
        float sc0 = gamma_p[r0] * inv,     bt0 = beta_p[r0];
        float sc8 = gamma_p[r0 + 8] * inv, bt8 = beta_p[r0 + 8];
        #pragma unroll
        for (int nt = 0; nt < 4; nt++) {
            #pragma unroll
            for (int e = 0; e < 2; e++) {
                int hw = hwv[nt][e];
                if (hw >= 0) {
                    out[((size_t)(b * COUT + r0)) * HW + hw]     = (f.acc[mt][nt][e]     * sc0 + bt0) * av[nt][e];
                    out[((size_t)(b * COUT + r0 + 8)) * HW + hw] = (f.acc[mt][nt][e + 2] * sc8 + bt8) * av[nt][e];
                }
            }
        }
    }
}

// ====== embed 1x1 (M=256=all E, N=64 q) + MMA attn: 256 thr, 2 CTAs/SM =====
#define E_BHI  32768
#define ESTG   40960       // A 32K | B 8K
#define ENSTEP 8
#define TSH 264                          // fp16 tile row stride (halves)
#define GSH_OFF (64 * TSH)               // g region offset (halves)
#define ESMEM 81920

struct FragE { float acc[4][4][4]; };

__device__ __forceinline__ void embed_load(uint32_t sb, int s, int q0, int b, int tid) {
    uint32_t st = sb + (uint32_t)(s & 1) * ESTG;
    const char* a_src = (const char*)(we_h + s * 64);
    size_t xoff = ((size_t)b * PBUF + XOFF + q0) * CIN + s * 64;
    const char* b_src = (const char*)(xp_hi + xoff);
    #pragma unroll
    for (int i = 0; i < 8; i++) {
        int id = tid + i * 256;
        int row = id >> 3, ch = id & 7;
        cp16(st + SW128(row * 128 + ch * 16), a_src + (size_t)row * 1024 + ch * 16);
    }
    #pragma unroll
    for (int i = 0; i < 2; i++) {
        int id = tid + i * 256;
        int row = id >> 3, ch = id & 7;
        cp16(st + E_BHI + SW128(row * 128 + ch * 16), b_src + (size_t)row * 1024 + ch * 16);
    }
    asm volatile("cp.async.commit_group;" ::: "memory");
}

__device__ __forceinline__ void mma_stepE(uint32_t st, int wm, int wn, int lane,
                                          FragE& f) {
    int lr    = lane & 15;
    int ahalf = ((lane >> 4) & 1) * 16;
    int brow  = ((lane >> 4) & 1) * 8 + (lane & 7);
    int bhalf = ((lane >> 3) & 1) * 16;
    #pragma unroll
    for (int kk = 0; kk < 4; kk++) {
        uint32_t bh[2][4];
        #pragma unroll
        for (int bt = 0; bt < 2; bt++) {
            uint32_t off = SW128((uint32_t)(wn * 32 + bt * 16 + brow) * 128 + kk * 32 + bhalf);
            LDSM_X4(bh[bt], st + E_BHI + off);
        }
        #pragma unroll
        for (int mt = 0; mt < 4; mt++) {
            uint32_t a[4];
            uint32_t off = SW128((uint32_t)(wm * 64 + mt * 16 + lr) * 128 + kk * 32 + ahalf);
            LDSM_X4(a, st + off);
            #pragma unroll
            for (int nt = 0; nt < 4; nt++) {
                int bt = nt >> 1, pp = (nt & 1) * 2;
                MMA16816(f.acc[mt][nt], a, bh[bt][pp], bh[bt][pp + 1]);
            }
        }
    }
}

__global__ void __launch_bounds__(256, 2)
embed_attn(const float* __restrict__ gamma_e,
           const float* __restrict__ beta_e,
           const float* __restrict__ head_bias) {
    extern __shared__ __align__(1024) char smem[];
    uint32_t sb = smem_u32(smem);
    int tid = threadIdx.x, wid = tid >> 5, lane = tid & 31;
    int q0 = blockIdx.x * 64;
    int b  = blockIdx.z;
    int wm = wid >> 1, wn = wid & 1;      // warp tile 64(E) x 32(q)

    FragE f;
    #pragma unroll
    for (int mt = 0; mt < 4; mt++)
        #pragma unroll
        for (int nt = 0; nt < 4; nt++)
            #pragma unroll
            for (int r = 0; r < 4; r++) f.acc[mt][nt][r] = 0.f;

    embed_load(sb, 0, q0, b, tid);
    for (int s = 0; s < ENSTEP; s++) {
        asm volatile("cp.async.wait_group 0;" ::: "memory");
        __syncthreads();
        if (s + 1 < ENSTEP) embed_load(sb, s + 1, q0, b, tid);
        mma_stepE(sb + (uint32_t)(s & 1) * ESTG, wm, wn, lane, f);
    }
    __syncthreads();   // stage buffers reused below

    // BN + write fp16 tile[q][e]
    __half* tile = reinterpret_cast<__half*>(smem);
    __half* gsm  = tile + GSH_OFF;
    float inv = rsqrtf(1.0f + BN_EPS);
    #pragma unroll
    for (int mt = 0; mt < 4; mt++) {
        int er = wm * 64 + mt * 16 + (lane >> 2);
        float sc0 = gamma_e[er] * inv,     bt0 = beta_e[er];
        float sc8 = gamma_e[er + 8] * inv, bt8 = beta_e[er + 8];
        #pragma unroll
        for (int nt = 0; nt < 4; nt++) {
            int ql = wn * 32 + nt * 8 + (lane & 3) * 2;
            tile[ql * TSH + er]           = __float2half(f.acc[mt][nt][0] * sc0 + bt0);
            tile[(ql + 1) * TSH + er]     = __float2half(f.acc[mt][nt][1] * sc0 + bt0);
            tile[ql * TSH + er + 8]       = __float2half(f.acc[mt][nt][2] * sc8 + bt8);
            tile[(ql + 1) * TSH + er + 8] = __float2half(f.acc[mt][nt][3] * sc8 + bt8);
        }
    }
    {
        const float* gsrc = g_buf + (size_t)b * NTOK * EE;
        for (int i = tid; i < NTOK * EE / 4; i += 256) {
            int n = i >> 6, eq = (i & 63) * 4;
            float4 v = reinterpret_cast<const float4*>(gsrc)[i];
            __half h4[4] = {__float2half(v.x), __float2half(v.y),
                            __float2half(v.z), __float2half(v.w)};
            *reinterpret_cast<uint2*>(&gsm[n * TSH + eq]) = *reinterpret_cast<const uint2*>(h4);
        }
    }
    __syncthreads();

    // ---- MMA attention scores: warp = head m, covers all 64 q ----
    int m  = wid;
    uint32_t tb = sb;
    uint32_t gb = sb + GSH_OFF * 2;
    int lr = lane & 15;
    int ah16 = ((lane >> 4) & 1) * 16;
    int brow = ((lane >> 4) & 1) * 8 + (lane & 7);
    int bh16 = ((lane >> 3) & 1) * 16;

    uint32_t a[4][2][4];
    #pragma unroll
    for (int mt = 0; mt < 4; mt++)
        #pragma unroll
        for (int kk = 0; kk < 2; kk++) {
            uint32_t addr = tb + (uint32_t)(mt * 16 + lr) * (TSH * 2)
                          + (m * 32 + kk * 16) * 2 + ah16;
            LDSM_X4(a[mt][kk], addr);
        }

    float rmax[4][2];
    #pragma unroll
    for (int mt = 0; mt < 4; mt++) { rmax[mt][0] = -3.4e38f; rmax[mt][1] = -3.4e38f; }

    #pragma unroll
    for (int nt16 = 0; nt16 < 5; nt16++) {
        uint32_t b0[4], b1[4];
        uint32_t baddr = gb + (uint32_t)(nt16 * 16 + brow) * (TSH * 2) + m * 32 * 2 + bh16;
        LDSM_X4(b0, baddr);
        LDSM_X4(b1, baddr + 32);
        #pragma unroll
        for (int sub = 0; sub < 2; sub++) {
            #pragma unroll
            for (int mt = 0; mt < 4; mt++) {
                float acc[4] = {0.f, 0.f, 0.f, 0.f};
                MMA16816(acc, a[mt][0], b0[sub * 2], b0[sub * 2 + 1]);
                MMA16816(acc, a[mt][1], b1[sub * 2], b1[sub * 2 + 1]);
                rmax[mt][0] = fmaxf(rmax[mt][0], fmaxf(acc[0], acc[1]));
                rmax[mt][1] = fmaxf(rmax[mt][1], fmaxf(acc[2], acc[3]));
            }
        }
    }

    float hb = head_bias[m];
    #pragma unroll
    for (int mt = 0; mt < 4; mt++) {
        #pragma unroll
        for (int r01 = 0; r01 < 2; r01++) {
            float v = rmax[mt][r01];
            v = fmaxf(v, __shfl_xor_sync(0xFFFFFFFFu, v, 1));
            v = fmaxf(v, __shfl_xor_sync(0xFFFFFFFFu, v, 2));
            if ((lane & 3) == 0) {
                int qq = q0 + mt * 16 + (lane >> 2) + r01 * 8;
                int pr = qq / 41, pc = qq - pr * 41;
                if (pc < 40 && pr < 40) {
                    float aa = v * 0.17677669529663687f + hb;
                    float s = 1.0f / (1.0f + __expf(-aa));
                    attn_buf[(size_t)(b * NH + m) * HW + pr * 40 + pc] = s;
                }
            }
        }
    }
}

extern "C" void kernel_launch(void* const* d_in, const int* in_sizes, int n_in,
                              void* d_out, int out_size) {
    const float* x         = (const float*)d_in[0];
    const float* guide     = (const float*)d_in[1];
    const float* We        = (const float*)d_in[2];
    const float* gamma_e   = (const float*)d_in[3];
    const float* beta_e    = (const float*)d_in[4];
    const float* Wg        = (const float*)d_in[5];
    const float* bg        = (const float*)d_in[6];
    const float* head_bias = (const float*)d_in[7];
    const float* Wp        = (const float*)d_in[8];
    const float* gamma_p   = (const float*)d_in[9];
    const float* beta_p    = (const float*)d_in[10];
    float* out = (float*)d_out;

    xprep<<<dim3(40, 8, 16), 256>>>(x);
    prep_wg<<<COUT + EE + 320, 256>>>(Wp, We, guide, Wg, bg);
    cudaFuncSetAttribute(embed_attn, cudaFuncAttributeMaxDynamicSharedMemorySize, ESMEM);
    embed_attn<<<dim3(26, 1, 16), 256, ESMEM>>>(gamma_e, beta_e, head_bias);
    cudaFuncSetAttribute(conv_mma, cudaFuncAttributeMaxDynamicSharedMemorySize, CSMEM);
    conv_mma<<<dim3(13, 4, 16), 256, CSMEM>>>(gamma_p, beta_p, out);
}

// round 17
// speedup vs baseline: 1.3585x; 1.2751x over previous
#include <cuda_runtime.h>
#include <cuda_fp16.h>
#include <cstdint>

#define BB   16
#define CIN  512
#define HH   40
#define WW   40
#define HW   1600
#define NTOK 80
#define CG   512
#define EE   256
#define COUT 512
#define NH   8
#define HC   32
#define BN_EPS 1e-3f
#define PBUF 1792
#define XOFF 64
#define NTILE 6400    // 16 b x 400 tiles (20x20 per image)

// ------------------------------ scratch (device globals) -------------------
__device__ float g_buf[BB * NTOK * EE];
__device__ float attn_buf[BB * NH * HW];
__device__ __align__(256) __half xp_hi[(size_t)BB * PBUF * CIN];
__device__ __align__(256) __half wt_h[(size_t)16 * COUT * CIN];   // U transforms
__device__ __align__(256) __half we_h[EE * CIN];
__device__ __align__(256) __half vbuf[(size_t)16 * NTILE * CIN];  // V transforms
__device__ __align__(256) float  mbuf[(size_t)16 * COUT * NTILE]; // GEMM results

// ------------------------------ helpers ------------------------------------
__device__ __forceinline__ uint32_t smem_u32(const void* p) {
    uint32_t a;
    asm("{ .reg .u64 t; cvta.to.shared.u64 t, %1; cvt.u32.u64 %0, t; }" : "=r"(a) : "l"(p));
    return a;
}
#define SW128(off) ((off) ^ (((off) >> 3) & 0x70))

__device__ __forceinline__ void cp16(uint32_t dst, const void* src) {
    asm volatile("cp.async.cg.shared.global [%0], [%1], 16;" :: "r"(dst), "l"(src));
}

#define LDSM_X4(r, a) \
    asm volatile("ldmatrix.sync.aligned.m8n8.x4.shared.b16 {%0,%1,%2,%3}, [%4];" \
        : "=r"((r)[0]), "=r"((r)[1]), "=r"((r)[2]), "=r"((r)[3]) : "r"(a))

#define MMA16816(d, a, b0, b1) \
    asm volatile("mma.sync.aligned.m16n8k16.row.col.f32.f16.f16.f32 " \
        "{%0,%1,%2,%3}, {%4,%5,%6,%7}, {%8,%9}, {%0,%1,%2,%3};" \
        : "+f"((d)[0]), "+f"((d)[1]), "+f"((d)[2]), "+f"((d)[3]) \
        : "r"((a)[0]), "r"((a)[1]), "r"((a)[2]), "r"((a)[3]), "r"(b0), "r"(b1))

// -------- merged prep: Wp -> wt_h (Winograd U), We -> we_h, guide FC --------
__global__ void prep_wg(const float* __restrict__ Wp, const float* __restrict__ We,
                        const float* __restrict__ guide, const float* __restrict__ Wg,
                        const float* __restrict__ bg) {
    int bid = blockIdx.x;
    if (bid < COUT) {
        int co = bid;
        int ci = threadIdx.x * 2;
        float u[2][16];
        #pragma unroll
        for (int e = 0; e < 2; e++) {
            const float* g = Wp + ((size_t)co * CIN + ci + e) * 9;
            float a[4][3];
            #pragma unroll
            for (int j = 0; j < 3; j++) {
                a[0][j] = g[j];
                a[1][j] = 0.5f * (g[j] + g[3 + j] + g[6 + j]);
                a[2][j] = 0.5f * (g[j] - g[3 + j] + g[6 + j]);
                a[3][j] = g[6 + j];
            }
            #pragma unroll
            for (int i = 0; i < 4; i++) {
                u[e][i * 4 + 0] = a[i][0];
                u[e][i * 4 + 1] = 0.5f * (a[i][0] + a[i][1] + a[i][2]);
                u[e][i * 4 + 2] = 0.5f * (a[i][0] - a[i][1] + a[i][2]);
                u[e][i * 4 + 3] = a[i][2];
            }
        }
        #pragma unroll
        for (int k = 0; k < 16; k++) {
            __half2 h = __floats2half2_rn(u[0][k], u[1][k]);
            *reinterpret_cast<__half2*>(&wt_h[((size_t)k * COUT + co) * CIN + ci]) = h;
        }
        return;
    }
    if (bid < COUT + EE) {
        int e = bid - COUT;
        for (int ci = threadIdx.x; ci < CIN; ci += 256)
            we_h[(size_t)e * CIN + ci] = __float2half(We[(size_t)e * CIN + ci]);
        return;
    }
    int gb = bid - COUT - EE;
    int row0 = (gb % 40) * 32;
    int col0 = (gb / 40) * 32;
    __shared__ float As[32][33];
    __shared__ float Bs[32][33];
    int tid = threadIdx.x;
    int tx = tid & 31, ty = tid >> 5;
    float acc[4] = {0.f, 0.f, 0.f, 0.f};
    for (int kc = 0; kc < CG; kc += 32) {
        int r = tid >> 3, kq = (tid & 7) * 4;
        float4 a4 = *reinterpret_cast<const float4*>(&guide[(size_t)(row0 + r) * CG + kc + kq]);
        As[r][kq] = a4.x; As[r][kq + 1] = a4.y; As[r][kq + 2] = a4.z; As[r][kq + 3] = a4.w;
        float4 b4 = *reinterpret_cast<const float4*>(&Wg[(size_t)(col0 + r) * CG + kc + kq]);
        Bs[r][kq] = b4.x; Bs[r][kq + 1] = b4.y; Bs[r][kq + 2] = b4.z; Bs[r][kq + 3] = b4.w;
        __syncthreads();
        #pragma unroll
        for (int k = 0; k < 32; k++) {
            float bv = Bs[tx][k];
            #pragma unroll
            for (int rr = 0; rr < 4; rr++)
                acc[rr] += As[ty + 8 * rr][k] * bv;
        }
        __syncthreads();
    }
    float bias = bg[col0 + tx];
    #pragma unroll
    for (int rr = 0; rr < 4; rr++)
        g_buf[(size_t)(row0 + ty + 8 * rr) * EE + col0 + tx] = acc[rr] + bias;
}

// x(r,c) -> padded fp16 at pi = r*41 + c; vectorized 16B stores; pads included
__global__ void xprep(const float* __restrict__ x) {
    __shared__ float s[64][41];
    int r  = blockIdx.x;
    int cc = blockIdx.y * 64;
    int b  = blockIdx.z;
    for (int idx = threadIdx.x; idx < 64 * 40; idx += 256) {
        int ci = idx / 40, c = idx % 40;
        s[ci][c] = x[((size_t)(b * CIN + cc + ci)) * HW + r * WW + c];
    }
    __syncthreads();
    for (int idx = threadIdx.x; idx < 41 * 8; idx += 256) {
        int c = idx >> 3, cg = idx & 7;
        __half h8[8];
        #pragma unroll
        for (int j = 0; j < 8; j++)
            h8[j] = __float2half((c < 40) ? s[cg * 8 + j][c] : 0.f);
        size_t off = ((size_t)b * PBUF + XOFF + r * 41 + c) * CIN + cc + cg * 8;
        *reinterpret_cast<uint4*>(&xp_hi[off]) = *reinterpret_cast<const uint4*>(h8);
    }
    if (r == 0) {
        uint4 z = {0, 0, 0, 0};
        for (int idx = threadIdx.x; idx < 152 * 8; idx += 256) {
            int sl = idx >> 3, cg = idx & 7;
            int slot = (sl < XOFF) ? sl : (XOFF + 1640 + sl - XOFF);
            *reinterpret_cast<uint4*>(&xp_hi[((size_t)b * PBUF + slot) * CIN + cc + cg * 8]) = z;
        }
    }
}

// -------- vtrans: V = B^T d B per (tile, 2ci), half2 arithmetic -------------
__global__ void vtrans() {
    int tid = threadIdx.x;
    int th  = blockIdx.x;          // 0..19
    int cib = blockIdx.y * 64;
    int b   = blockIdx.z;
    int tw  = tid >> 5;            // 0..19 (block 640 threads)
    int cig = tid & 31;
    int ci  = cib + cig * 2;
    int ro = 2 * th - 1, co_ = 2 * tw - 1;

    __half2 d[4][4];
    #pragma unroll
    for (int i = 0; i < 4; i++)
        #pragma unroll
        for (int j = 0; j < 4; j++) {
            int idx = XOFF + (ro + i) * 41 + co_ + j;
            d[i][j] = *reinterpret_cast<const __half2*>(
                &xp_hi[((size_t)b * PBUF + idx) * CIN + ci]);
        }
    __half2 t[4][4];
    #pragma unroll
    for (int j = 0; j < 4; j++) {
        t[0][j] = __hsub2(d[0][j], d[2][j]);
        t[1][j] = __hadd2(d[1][j], d[2][j]);
        t[2][j] = __hsub2(d[2][j], d[1][j]);
        t[3][j] = __hsub2(d[1][j], d[3][j]);
    }
    size_t tg = (size_t)b * 400 + th * 20 + tw;
    #pragma unroll
    for (int k = 0; k < 4; k++) {
        __half2 v0 = __hsub2(t[k][0], t[k][2]);
        __half2 v1 = __hadd2(t[k][1], t[k][2]);
        __half2 v2 = __hsub2(t[k][2], t[k][1]);
        __half2 v3 = __hsub2(t[k][1], t[k][3]);
        *reinterpret_cast<__half2*>(&vbuf[((size_t)(k * 4 + 0) * NTILE + tg) * CIN + ci]) = v0;
        *reinterpret_cast<__half2*>(&vbuf[((size_t)(k * 4 + 1) * NTILE + tg) * CIN + ci]) = v1;
        *reinterpret_cast<__half2*>(&vbuf[((size_t)(k * 4 + 2) * NTILE + tg) * CIN + ci]) = v2;
        *reinterpret_cast<__half2*>(&vbuf[((size_t)(k * 4 + 3) * NTILE + tg) * CIN + ci]) = v3;
    }
}

// ===== wino GEMM: CTA 128(co) x 128(tiles), 8 warps 64x32, 2 CTAs/SM ========
#define C_BHI  16384
#define CSTG   32768       // A 16K | B 16K
#define CSMEM  98304       // 3 stages
#define WSTEP  8

struct FragC { float acc[4][4][4]; };

__device__ __forceinline__ void wino_load(uint32_t sb, int s, int cobase,
                                          int tile0, int pt, int tid) {
    uint32_t st = sb + (uint32_t)(s % 3) * CSTG;
    const char* a_src = (const char*)(wt_h + ((size_t)pt * COUT + cobase) * CIN + s * 64);
    const char* b_src = (const char*)(vbuf + ((size_t)pt * NTILE + tile0) * CIN + s * 64);
    #pragma unroll
    for (int i = 0; i < 4; i++) {
        int id = tid + i * 256;
        int row = id >> 3, ch = id & 7;
        cp16(st + SW128(row * 128 + ch * 16), a_src + (size_t)row * 1024 + ch * 16);
    }
    #pragma unroll
    for (int i = 0; i < 4; i++) {
        int id = tid + i * 256;
        int row = id >> 3, ch = id & 7;
        cp16(st + C_BHI + SW128(row * 128 + ch * 16), b_src + (size_t)row * 1024 + ch * 16);
    }
    asm volatile("cp.async.commit_group;" ::: "memory");
}

__device__ __forceinline__ void mma_stepC(uint32_t st, int wm, int wn, int lane,
                                          FragC& f) {
    int lr    = lane & 15;
    int ahalf = ((lane >> 4) & 1) * 16;
    int brow  = ((lane >> 4) & 1) * 8 + (lane & 7);
    int bhalf = ((lane >> 3) & 1) * 16;
    uint32_t bh[4][2][4];
    #pragma unroll
    for (int kk = 0; kk < 4; kk++)
        #pragma unroll
        for (int bt = 0; bt < 2; bt++) {
            uint32_t off = SW128((uint32_t)(wn * 32 + bt * 16 + brow) * 128 + kk * 32 + bhalf);
            LDSM_X4(bh[kk][bt], st + C_BHI + off);
        }
    #pragma unroll
    for (int kk = 0; kk < 4; kk++) {
        #pragma unroll
        for (int mt = 0; mt < 4; mt++) {
            uint32_t a[4];
            uint32_t off = SW128((uint32_t)(wm * 64 + mt * 16 + lr) * 128 + kk * 32 + ahalf);
            LDSM_X4(a, st + off);
            #pragma unroll
            for (int nt = 0; nt < 4; nt++) {
                int bt = nt >> 1, pp = (nt & 1) * 2;
                MMA16816(f.acc[mt][nt], a, bh[kk][bt][pp], bh[kk][bt][pp + 1]);
            }
        }
    }
}

__global__ void __launch_bounds__(256, 2)
wino_mma() {
    extern __shared__ __align__(1024) char smem[];
    uint32_t sb = smem_u32(smem);
    int tid = threadIdx.x, wid = tid >> 5, lane = tid & 31;
    int tile0  = blockIdx.x * 128;
    int cobase = blockIdx.y * 128;
    int pt     = blockIdx.z;
    int wm = wid >> 2, wn = wid & 3;

    FragC f;
    #pragma unroll
    for (int mt = 0; mt < 4; mt++)
        #pragma unroll
        for (int nt = 0; nt < 4; nt++)
            #pragma unroll
            for (int r = 0; r < 4; r++) f.acc[mt][nt][r] = 0.f;

    wino_load(sb, 0, cobase, tile0, pt, tid);
    wino_load(sb, 1, cobase, tile0, pt, tid);
    for (int s = 0; s < WSTEP; s++) {
        if (s + 1 < WSTEP) asm volatile("cp.async.wait_group 1;" ::: "memory");
        else               asm volatile("cp.async.wait_group 0;" ::: "memory");
        __syncthreads();
        if (s + 2 < WSTEP) wino_load(sb, s + 2, cobase, tile0, pt, tid);
        mma_stepC(sb + (uint32_t)(s % 3) * CSTG, wm, wn, lane, f);
    }

    float* mb = mbuf + (size_t)pt * COUT * NTILE;
    #pragma unroll
    for (int mt = 0; mt < 4; mt++) {
        int r0 = cobase + wm * 64 + mt * 16 + (lane >> 2);
        #pragma unroll
        for (int nt = 0; nt < 4; nt++) {
            int col = tile0 + wn * 32 + nt * 8 + (lane & 3) * 2;
            float2 v0 = {f.acc[mt][nt][0], f.acc[mt][nt][1]};
            float2 v1 = {f.acc[mt][nt][2], f.acc[mt][nt][3]};
            *reinterpret_cast<float2*>(&mb[(size_t)r0 * NTILE + col]) = v0;
            *reinterpret_cast<float2*>(&mb[(size_t)(r0 + 8) * NTILE + col]) = v1;
        }
    }
}

// -------- wino_out: out = A^T M A, fused BN + sigmoid gate ------------------
__global__ void wino_out(const float* __restrict__ gamma_p,
                         const float* __restrict__ beta_p,
                         float* __restrict__ out) {
    int tid = threadIdx.x;
    int tl = blockIdx.x * 128 + (tid & 127);
    int co = blockIdx.y * 2 + (tid >> 7);
    int b = tl / 400, rem = tl - b * 400;
    int th = rem / 20, tw = rem - th * 20;

    float M[4][4];
    #pragma unroll
    for (int k = 0; k < 16; k++)
        M[k >> 2][k & 3] = mbuf[(size_t)k * COUT * NTILE + (size_t)co * NTILE + tl];

    float s0[4], s1[4];
    #pragma unroll
    for (int j = 0; j < 4; j++) {
        s0[j] = M[0][j] + M[1][j] + M[2][j];
        s1[j] = M[1][j] - M[2][j] - M[3][j];
    }
    float o00 = s0[0] + s0[1] + s0[2];
    float o01 = s0[1] - s0[2] - s0[3];
    float o10 = s1[0] + s1[1] + s1[2];
    float o11 = s1[1] - s1[2] - s1[3];

    float inv = rsqrtf(1.0f + BN_EPS);
    float sc = gamma_p[co] * inv;
    float bt = beta_p[co];
    int head = co >> 6;
    int hw0 = (2 * th) * 40 + 2 * tw;
    const float* ap = &attn_buf[(size_t)(b * NH + head) * HW];
    float2 a0 = *reinterpret_cast<const float2*>(&ap[hw0]);
    float2 a1 = *reinterpret_cast<const float2*>(&ap[hw0 + 40]);
    float2 v0 = {(o00 * sc + bt) * a0.x, (o01 * sc + bt) * a0.y};
    float2 v1 = {(o10 * sc + bt) * a1.x, (o11 * sc + bt) * a1.y};
    float* op = &out[((size_t)(b * COUT + co)) * HW];
    *reinterpret_cast<float2*>(&op[hw0]) = v0;
    *reinterpret_cast<float2*>(&op[hw0 + 40]) = v1;
}

// ====== embed 1x1 (M=256=all E, N=64 q) + MMA attn: 256 thr, 2 CTAs/SM =====
#define E_BHI  32768
#define ESTG   40960       // A 32K | B 8K
#define ENSTEP 8
#define TSH 264
#define GSH_OFF (64 * TSH)
#define ESMEM 81920

struct FragE { float acc[4][4][4]; };

__device__ __forceinline__ void embed_load(uint32_t sb, int s, int q0, int b, int tid) {
    uint32_t st = sb + (uint32_t)(s & 1) * ESTG;
    const char* a_src = (const char*)(we_h + s * 64);
    size_t xoff = ((size_t)b * PBUF + XOFF + q0) * CIN + s * 64;
    const char* b_src = (const char*)(xp_hi + xoff);
    #pragma unroll
    for (int i = 0; i < 8; i++) {
        int id = tid + i * 256;
        int row = id >> 3, ch = id & 7;
        cp16(st + SW128(row * 128 + ch * 16), a_src + (size_t)row * 1024 + ch * 16);
    }
    #pragma unroll
    for (int i = 0; i < 2; i++) {
        int id = tid + i * 256;
        int row = id >> 3, ch = id & 7;
        cp16(st + E_BHI + SW128(row * 128 + ch * 16), b_src + (size_t)row * 1024 + ch * 16);
    }
    asm volatile("cp.async.commit_group;" ::: "memory");
}

__device__ __forceinline__ void mma_stepE(uint32_t st, int wm, int wn, int lane,
                                          FragE& f) {
    int lr    = lane & 15;
    int ahalf = ((lane >> 4) & 1) * 16;
    int brow  = ((lane >> 4) & 1) * 8 + (lane & 7);
    int bhalf = ((lane >> 3) & 1) * 16;
    #pragma unroll
    for (int kk = 0; kk < 4; kk++) {
        uint32_t bh[2][4];
        #pragma unroll
        for (int bt = 0; bt < 2; bt++) {
            uint32_t off = SW128((uint32_t)(wn * 32 + bt * 16 + brow) * 128 + kk * 32 + bhalf);
            LDSM_X4(bh[bt], st + E_BHI + off);
        }
        #pragma unroll
        for (int mt = 0; mt < 4; mt++) {
            uint32_t a[4];
            uint32_t off = SW128((uint32_t)(wm * 64 + mt * 16 + lr) * 128 + kk * 32 + ahalf);
            LDSM_X4(a, st + off);
            #pragma unroll
            for (int nt = 0; nt < 4; nt++) {
                int bt = nt >> 1, pp = (nt & 1) * 2;
                MMA16816(f.acc[mt][nt], a, bh[bt][pp], bh[bt][pp + 1]);
            }
        }
    }
}

__global__ void __launch_bounds__(256, 2)
embed_attn(const float* __restrict__ gamma_e,
           const float* __restrict__ beta_e,
           const float* __restrict__ head_bias) {
    extern __shared__ __align__(1024) char smem[];
    uint32_t sb = smem_u32(smem);
    int tid = threadIdx.x, wid = tid >> 5, lane = tid & 31;
    int q0 = blockIdx.x * 64;
    int b  = blockIdx.z;
    int wm = wid >> 1, wn = wid & 1;

    FragE f;
    #pragma unroll
    for (int mt = 0; mt < 4; mt++)
        #pragma unroll
        for (int nt = 0; nt < 4; nt++)
            #pragma unroll
            for (int r = 0; r < 4; r++) f.acc[mt][nt][r] = 0.f;

    embed_load(sb, 0, q0, b, tid);
    for (int s = 0; s < ENSTEP; s++) {
        asm volatile("cp.async.wait_group 0;" ::: "memory");
        __syncthreads();
        if (s + 1 < ENSTEP) embed_load(sb, s + 1, q0, b, tid);
        mma_stepE(sb + (uint32_t)(s & 1) * ESTG, wm, wn, lane, f);
    }
    __syncthreads();

    __half* tile = reinterpret_cast<__half*>(smem);
    __half* gsm  = tile + GSH_OFF;
    float inv = rsqrtf(1.0f + BN_EPS);
    #pragma unroll
    for (int mt = 0; mt < 4; mt++) {
        int er = wm * 64 + mt * 16 + (lane >> 2);
        float sc0 = gamma_e[er] * inv,     bt0 = beta_e[er];
        float sc8 = gamma_e[er + 8] * inv, bt8 = beta_e[er + 8];
        #pragma unroll
        for (int nt = 0; nt < 4; nt++) {
            int ql = wn * 32 + nt * 8 + (lane & 3) * 2;
            tile[ql * TSH + er]           = __float2half(f.acc[mt][nt][0] * sc0 + bt0);
            tile[(ql + 1) * TSH + er]     = __float2half(f.acc[mt][nt][1] * sc0 + bt0);
            tile[ql * TSH + er + 8]       = __float2half(f.acc[mt][nt][2] * sc8 + bt8);
            tile[(ql + 1) * TSH + er + 8] = __float2half(f.acc[mt][nt][3] * sc8 + bt8);
        }
    }
    {
        const float* gsrc = g_buf + (size_t)b * NTOK * EE;
        for (int i = tid; i < NTOK * EE / 4; i += 256) {
            int n = i >> 6, eq = (i & 63) * 4;
            float4 v = reinterpret_cast<const float4*>(gsrc)[i];
            __half h4[4] = {__float2half(v.x), __float2half(v.y),
                            __float2half(v.z), __float2half(v.w)};
            *reinterpret_cast<uint2*>(&gsm[n * TSH + eq]) = *reinterpret_cast<const uint2*>(h4);
        }
    }
    __syncthreads();

    int m  = wid;
    uint32_t tb = sb;
    uint32_t gb = sb + GSH_OFF * 2;
    int lr = lane & 15;
    int ah16 = ((lane >> 4) & 1) * 16;
    int brow = ((lane >> 4) & 1) * 8 + (lane & 7);
    int bh16 = ((lane >> 3) & 1) * 16;

    uint32_t a[4][2][4];
    #pragma unroll
    for (int mt = 0; mt < 4; mt++)
        #pragma unroll
        for (int kk = 0; kk < 2; kk++) {
            uint32_t addr = tb + (uint32_t)(mt * 16 + lr) * (TSH * 2)
                          + (m * 32 + kk * 16) * 2 + ah16;
            LDSM_X4(a[mt][kk], addr);
        }

    float rmax[4][2];
    #pragma unroll
    for (int mt = 0; mt < 4; mt++) { rmax[mt][0] = -3.4e38f; rmax[mt][1] = -3.4e38f; }

    #pragma unroll
    for (int nt16 = 0; nt16 < 5; nt16++) {
        uint32_t b0[4], b1[4];
        uint32_t baddr = gb + (uint32_t)(nt16 * 16 + brow) * (TSH * 2) + m * 32 * 2 + bh16;
        LDSM_X4(b0, baddr);
        LDSM_X4(b1, baddr + 32);
        #pragma unroll
        for (int sub = 0; sub < 2; sub++) {
            #pragma unroll
            for (int mt = 0; mt < 4; mt++) {
                float acc[4] = {0.f, 0.f, 0.f, 0.f};
                MMA16816(acc, a[mt][0], b0[sub * 2], b0[sub * 2 + 1]);
                MMA16816(acc, a[mt][1], b1[sub * 2], b1[sub * 2 + 1]);
                rmax[mt][0] = fmaxf(rmax[mt][0], fmaxf(acc[0], acc[1]));
                rmax[mt][1] = fmaxf(rmax[mt][1], fmaxf(acc[2], acc[3]));
            }
        }
    }

    float hb = head_bias[m];
    #pragma unroll
    for (int mt = 0; mt < 4; mt++) {
        #pragma unroll
        for (int r01 = 0; r01 < 2; r01++) {
            float v = rmax[mt][r01];
            v = fmaxf(v, __shfl_xor_sync(0xFFFFFFFFu, v, 1));
            v = fmaxf(v, __shfl_xor_sync(0xFFFFFFFFu, v, 2));
            if ((lane & 3) == 0) {
                int qq = q0 + mt * 16 + (lane >> 2) + r01 * 8;
                int pr = qq / 41, pc = qq - pr * 41;
                if (pc < 40 && pr < 40) {
                    float aa = v * 0.17677669529663687f + hb;
                    float s = 1.0f / (1.0f + __expf(-aa));
                    attn_buf[(size_t)(b * NH + m) * HW + pr * 40 + pc] = s;
                }
            }
        }
    }
}

extern "C" void kernel_launch(void* const* d_in, const int* in_sizes, int n_in,
                              void* d_out, int out_size) {
    const float* x         = (const float*)d_in[0];
    const float* guide     = (const float*)d_in[1];
    const float* We        = (const float*)d_in[2];
    const float* gamma_e   = (const float*)d_in[3];
    const float* beta_e    = (const float*)d_in[4];
    const float* Wg        = (const float*)d_in[5];
    const float* bg        = (const float*)d_in[6];
    const float* head_bias = (const float*)d_in[7];
    const float* Wp        = (const float*)d_in[8];
    const float* gamma_p   = (const float*)d_in[9];
    const float* beta_p    = (const float*)d_in[10];
    float* out = (float*)d_out;

    xprep<<<dim3(40, 8, 16), 256>>>(x);
    prep_wg<<<COUT + EE + 320, 256>>>(Wp, We, guide, Wg, bg);
    vtrans<<<dim3(20, 8, 16), 640>>>();
    cudaFuncSetAttribute(embed_attn, cudaFuncAttributeMaxDynamicSharedMemorySize, ESMEM);
    embed_attn<<<dim3(26, 1, 16), 256, ESMEM>>>(gamma_e, beta_e, head_bias);
    cudaFuncSetAttribute(wino_mma, cudaFuncAttributeMaxDynamicSharedMemorySize, CSMEM);
    wino_mma<<<dim3(50, 4, 16), 256, CSMEM>>>();
    wino_out<<<dim3(50, 256), 256>>>(gamma_p, beta_p, out);
}